// round 7
// baseline (speedup 1.0000x reference)
#include <cuda_runtime.h>
#include <cuda_bf16.h>
#include <math.h>

// ---------------- problem constants ----------------
#define BB   8
#define NN   3136        // 56*56
#define DM   512
#define NH   4
#define DK   128         // head_qk
#define DV   256         // head_v
#define CH   64          // chunk
#define NC   49          // chunks per sequence
#define MTOT (BB*NN)     // 25088
#define NSEQ 64          // 2 dir * 8 b * 4 h

// padded smem strides
#define PDK 132
#define PDV 260
#define PCH 68

// ---------------- scratch (device globals; no allocation) ----------------
__device__ float g_xs  [MTOT * DM];          // conv+silu output
__device__ float g_qkv [MTOT * 2048];        // q(512) k(512) v(1024)
__device__ float g_t16 [MTOT * 16];          // low-rank intermediate
__device__ float g_gk  [MTOT * 1024];        // gates (f 512 | b 512), log-sig/16
__device__ float g_g   [MTOT * 1024];        // output gate pre-silu
__device__ float g_qe  [(size_t)NSEQ * NN * DK];    // decayed scaled q per seq
__device__ float g_od  [2][(size_t)32 * NN * DV];   // o_fwd / o_bwd (orig positions)
__device__ float g_S   [(size_t)NSEQ * NC * DK * DV]; // local states -> prefix states
__device__ float g_dec [NSEQ * NC * DK];     // per-chunk decay exp(btot)
__device__ float g_ob  [MTOT * 1024];        // gated combined output

// ---------------- depthwise conv 3x3 + SiLU ----------------
__global__ void __launch_bounds__(256) conv_silu_kernel(
    const float* __restrict__ x, const float* __restrict__ w)
{
    int idx = blockIdx.x * 256 + threadIdx.x;       // over MTOT*512
    int c = idx & 511;
    int m = idx >> 9;
    int b = m / NN;
    int n = m - b * NN;
    int h = n / 56, ww = n - h * 56;
    float acc = 0.f;
    #pragma unroll
    for (int dh = -1; dh <= 1; dh++) {
        int hh = h + dh;
        if ((unsigned)hh >= 56u) continue;
        #pragma unroll
        for (int dw = -1; dw <= 1; dw++) {
            int w2 = ww + dw;
            if ((unsigned)w2 >= 56u) continue;
            acc += x[(((size_t)b * NN + hh * 56 + w2) << 9) + c] * w[c * 9 + (dh + 1) * 3 + (dw + 1)];
        }
    }
    g_xs[idx] = acc / (1.f + expf(-acc));
}

// ---------------- tiled GEMM: C[M,Nc] = A[M,K] * B[Nc,K]^T (+bias, +opt act) ----------------
// 128x128 tile, BK=8, 256 threads, 8x8 microtile, register prefetch of next k-tile.
// act==1: C = logsigmoid(C)/16  (for the gate path)
__global__ void __launch_bounds__(256) gemm_nt_kernel(
    const float* __restrict__ A, const float* __restrict__ Bm,
    const float* __restrict__ bias, float* __restrict__ C, int K, int Nc, int act)
{
    __shared__ float As[8][128];
    __shared__ float Bs[8][128];
    const int tid = threadIdx.x;
    const int m0 = blockIdx.y * 128;
    const int n0 = blockIdx.x * 128;
    const int tx = tid & 15, ty = tid >> 4;

    // load mapping: each thread loads one float4 of A and one of B per k-tile
    const int lr = tid >> 1;             // 0..127 row within tile
    const int lk = (tid & 1) * 4;        // 0 or 4 within BK=8
    const float* Ap = A + (size_t)(m0 + lr) * K + lk;
    const float* Bp = Bm + (size_t)(n0 + lr) * K + lk;

    float acc[8][8] = {};

    float4 av = *(const float4*)(Ap);
    float4 bv = *(const float4*)(Bp);

    for (int k0 = 0; k0 < K; k0 += 8) {
        As[lk + 0][lr] = av.x; As[lk + 1][lr] = av.y; As[lk + 2][lr] = av.z; As[lk + 3][lr] = av.w;
        Bs[lk + 0][lr] = bv.x; Bs[lk + 1][lr] = bv.y; Bs[lk + 2][lr] = bv.z; Bs[lk + 3][lr] = bv.w;
        __syncthreads();
        if (k0 + 8 < K) {                 // prefetch next tile while computing this one
            av = *(const float4*)(Ap + k0 + 8);
            bv = *(const float4*)(Bp + k0 + 8);
        }
        #pragma unroll
        for (int kk = 0; kk < 8; kk++) {
            float a[8], bb[8];
            *(float4*)&a[0]  = *(const float4*)&As[kk][ty * 8 + 0];
            *(float4*)&a[4]  = *(const float4*)&As[kk][ty * 8 + 4];
            *(float4*)&bb[0] = *(const float4*)&Bs[kk][tx * 8 + 0];
            *(float4*)&bb[4] = *(const float4*)&Bs[kk][tx * 8 + 4];
            #pragma unroll
            for (int i = 0; i < 8; i++)
                #pragma unroll
                for (int j = 0; j < 8; j++) acc[i][j] += a[i] * bb[j];
        }
        __syncthreads();
    }
    // epilogue: bias add, optional activation, vectorized 128-bit stores
    if (bias) {
        float bvreg[8];
        *(float4*)&bvreg[0] = *(const float4*)&bias[n0 + tx * 8 + 0];
        *(float4*)&bvreg[4] = *(const float4*)&bias[n0 + tx * 8 + 4];
        #pragma unroll
        for (int i = 0; i < 8; i++)
            #pragma unroll
            for (int j = 0; j < 8; j++) acc[i][j] += bvreg[j];
    }
    if (act == 1) {
        #pragma unroll
        for (int i = 0; i < 8; i++)
            #pragma unroll
            for (int j = 0; j < 8; j++) {
                float v = acc[i][j];
                acc[i][j] = (fminf(v, 0.f) - log1pf(expf(-fabsf(v)))) * (1.f / 16.f);
            }
    }
    #pragma unroll
    for (int i = 0; i < 8; i++) {
        int m = m0 + ty * 8 + i;
        float* crow = C + (size_t)m * Nc + n0 + tx * 8;
        *(float4*)(crow + 0) = *(const float4*)&acc[i][0];
        *(float4*)(crow + 4) = *(const float4*)&acc[i][4];
    }
}

// ---------------- low-rank gate, stage 1: t16 = xs @ gk_w1^T ----------------
// 64 rows/block; w1 staged transposed in smem; xs tiled in 128-col chunks.
__global__ void __launch_bounds__(256) lowrank1_kernel(const float* __restrict__ w1)
{
    __shared__ float w1t[128][16];   // transposed chunk of w1: [c][r]
    __shared__ float xs_s[64][129];  // xs chunk, padded stride
    const int tid = threadIdx.x;
    const int m0 = blockIdx.x * 64;
    const int tx = tid & 15;         // r index
    const int ty = tid >> 4;         // row group (4 rows each)

    float acc[4] = {};

    for (int c0 = 0; c0 < 512; c0 += 128) {
        // stage w1 chunk transposed: 128x16 floats, 8 per thread
        for (int e = tid; e < 128 * 16; e += 256) {
            int c = e >> 4, r = e & 15;
            w1t[c][r] = w1[r * 512 + c0 + c];
        }
        // stage xs chunk: 64 rows x 128 cols, float4 loads
        for (int e = tid; e < 64 * 32; e += 256) {
            int row = e >> 5, cq = (e & 31) << 2;
            float4 v = *(const float4*)&g_xs[(size_t)(m0 + row) * 512 + c0 + cq];
            xs_s[row][cq + 0] = v.x; xs_s[row][cq + 1] = v.y;
            xs_s[row][cq + 2] = v.z; xs_s[row][cq + 3] = v.w;
        }
        __syncthreads();
        #pragma unroll 4
        for (int c = 0; c < 128; c++) {
            float w = w1t[c][tx];
            #pragma unroll
            for (int i = 0; i < 4; i++)
                acc[i] += xs_s[ty * 4 + i][c] * w;
        }
        __syncthreads();
    }
    #pragma unroll
    for (int i = 0; i < 4; i++)
        g_t16[(m0 + ty * 4 + i) * 16 + tx] = acc[i];
}

// ---------------- GLA phase 1: per-chunk intra attention + local state ----------------
// grid: NSEQ*NC blocks; dynamic smem layout below.
#define SM1_FLOATS (3 * 64 * PDK + 64 * PDV + 64 * PCH + 128)
__global__ void __launch_bounds__(256) gla1_kernel()
{
    extern __shared__ float sm[];
    float* sB = sm;                   // [64][PDK] cumsum gates
    float* sQ = sB + 64 * PDK;        // [64][PDK] qe
    float* sK = sQ + 64 * PDK;        // [64][PDK] k*exp(-b)
    float* sV = sK + 64 * PDK;        // [64][PDV] v
    float* sA = sV + 64 * PDV;        // [64][PCH] masked scores
    float* sE = sA + 64 * PCH;        // [128] exp(btot)

    const int blk = blockIdx.x;
    const int c = blk % NC;
    const int seq = blk / NC;
    const int h = seq & 3;
    const int b = (seq >> 2) & 7;
    const int dir = seq >> 5;
    const int tid = threadIdx.x;

    // load raw gates for this chunk
    for (int e = tid; e < 64 * 128; e += 256) {
        int t = e >> 7, d = e & 127;
        int pos = dir ? (NN - 1 - (c * CH + t)) : (c * CH + t);
        sB[t * PDK + d] = g_gk[((size_t)(b * NN + pos)) * 1024 + dir * 512 + h * 128 + d];
    }
    __syncthreads();
    // inclusive cumsum over t per d; record exp(btot) and decay
    if (tid < 128) {
        float run = sB[tid];
        for (int t = 1; t < 64; t++) { run += sB[t * PDK + tid]; sB[t * PDK + tid] = run; }
        float eb = expf(run);
        sE[tid] = eb;
        g_dec[(seq * NC + c) * 128 + tid] = eb;
    }
    __syncthreads();
    // qe / ke
    const float scale = 0.08838834764831845f;   // 128^-0.5
    for (int e = tid; e < 64 * 128; e += 256) {
        int t = e >> 7, d = e & 127;
        int pos = dir ? (NN - 1 - (c * CH + t)) : (c * CH + t);
        float bb = sB[t * PDK + d];
        size_t rowq = ((size_t)(b * NN + pos)) * 2048 + h * 128 + d;
        float qe = g_qkv[rowq] * expf(bb) * scale;
        float ke = g_qkv[rowq + 512] * expf(-bb);
        sQ[t * PDK + d] = qe;
        sK[t * PDK + d] = ke;
        g_qe[((size_t)seq * NN + c * CH + t) * 128 + d] = qe;
    }
    // v
    for (int e = tid; e < 64 * 256; e += 256) {
        int t = e >> 8, j = e & 255;
        int pos = dir ? (NN - 1 - (c * CH + t)) : (c * CH + t);
        sV[t * PDV + j] = g_qkv[((size_t)(b * NN + pos)) * 2048 + 1024 + h * 256 + j];
    }
    __syncthreads();

    const int tx = tid & 15, ty = tid >> 4;
    // A[t][s] = qe_t . ke_s, causal mask
    {
        float acc[4][4] = {};
        for (int d = 0; d < 128; d++) {
            float a[4], bb[4];
            #pragma unroll
            for (int i = 0; i < 4; i++) a[i] = sQ[(ty * 4 + i) * PDK + d];
            #pragma unroll
            for (int j = 0; j < 4; j++) bb[j] = sK[(tx * 4 + j) * PDK + d];
            #pragma unroll
            for (int i = 0; i < 4; i++)
                #pragma unroll
                for (int j = 0; j < 4; j++) acc[i][j] += a[i] * bb[j];
        }
        #pragma unroll
        for (int i = 0; i < 4; i++)
            #pragma unroll
            for (int j = 0; j < 4; j++) {
                int t = ty * 4 + i, s = tx * 4 + j;
                sA[t * PCH + s] = (t >= s) ? acc[i][j] : 0.f;
            }
    }
    __syncthreads();
    // o_intra = A @ v  (4 t x 16 j per thread)
    {
        float acc[4][16] = {};
        int t0 = ty * 4, j0 = tx * 16;
        for (int s = 0; s < 64; s++) {
            float a[4];
            #pragma unroll
            for (int i = 0; i < 4; i++) a[i] = sA[(t0 + i) * PCH + s];
            #pragma unroll
            for (int j = 0; j < 16; j++) {
                float vv = sV[s * PDV + j0 + j];
                #pragma unroll
                for (int i = 0; i < 4; i++) acc[i][j] += a[i] * vv;
            }
        }
        #pragma unroll
        for (int i = 0; i < 4; i++) {
            int t = t0 + i;
            int pos = dir ? (NN - 1 - (c * CH + t)) : (c * CH + t);
            float* dst = &g_od[dir][((size_t)(b * 4 + h) * NN + pos) * 256 + j0];
            #pragma unroll
            for (int j = 0; j < 16; j++) dst[j] = acc[i][j];
        }
    }
    // local state: S_loc[d][j] = exp(btot_d) * sum_t ke[t][d] * v[t][j]
    {
        int d0 = ty * 8;
        for (int jh = 0; jh < 2; jh++) {
            int j0 = jh * 128 + tx * 8;
            float acc[8][8] = {};
            for (int s = 0; s < 64; s++) {
                float kv[8], vv[8];
                #pragma unroll
                for (int i = 0; i < 8; i++) kv[i] = sK[s * PDK + d0 + i];
                #pragma unroll
                for (int j = 0; j < 8; j++) vv[j] = sV[s * PDV + j0 + j];
                #pragma unroll
                for (int i = 0; i < 8; i++)
                    #pragma unroll
                    for (int j = 0; j < 8; j++) acc[i][j] += kv[i] * vv[j];
            }
            size_t base = ((size_t)(seq * NC + c)) * 32768;
            #pragma unroll
            for (int i = 0; i < 8; i++) {
                float eb = sE[d0 + i];
                #pragma unroll
                for (int j = 0; j < 8; j++)
                    g_S[base + (d0 + i) * 256 + j0 + j] = eb * acc[i][j];
            }
        }
    }
}

// ---------------- GLA phase 2: sequential scan over chunks (in place) ----------------
__global__ void __launch_bounds__(256) gla_scan_kernel()
{
    int g = blockIdx.x * 256 + threadIdx.x;     // < NSEQ*128*256
    int j = g & 255;
    int d = (g >> 8) & 127;
    int seq = g >> 15;
    float S = 0.f;
    size_t base = (size_t)seq * NC * 32768 + d * 256 + j;
    int dbase = seq * NC * 128 + d;
    for (int c = 0; c < NC; c++) {
        float loc = g_S[base + (size_t)c * 32768];
        float dec = g_dec[dbase + c * 128];
        g_S[base + (size_t)c * 32768] = S;       // prefix (state BEFORE chunk c)
        S = S * dec + loc;
    }
}

// ---------------- GLA phase 3: o += qe @ S_prefix ----------------
#define SM3_FLOATS (64 * PDK + 128 * PDV)
__global__ void __launch_bounds__(256) gla3_kernel()
{
    const int blk = blockIdx.x;
    const int c = blk % NC;
    if (c == 0) return;                          // prefix is zero
    const int seq = blk / NC;
    const int h = seq & 3;
    const int b = (seq >> 2) & 7;
    const int dir = seq >> 5;
    const int tid = threadIdx.x;

    extern __shared__ float sm[];
    float* sQ = sm;                  // [64][PDK]
    float* sS = sQ + 64 * PDK;       // [128][PDV]

    for (int e = tid; e < 64 * 128; e += 256) {
        int t = e >> 7, d = e & 127;
        sQ[t * PDK + d] = g_qe[((size_t)seq * NN + c * CH + t) * 128 + d];
    }
    size_t sbase = ((size_t)(seq * NC + c)) * 32768;
    for (int e = tid; e < 128 * 256; e += 256) {
        int d = e >> 8, j = e & 255;
        sS[d * PDV + j] = g_S[sbase + e];
    }
    __syncthreads();

    const int tx = tid & 15, ty = tid >> 4;
    int t0 = ty * 4, j0 = tx * 16;
    float acc[4][16] = {};
    for (int d = 0; d < 128; d++) {
        float a[4];
        #pragma unroll
        for (int i = 0; i < 4; i++) a[i] = sQ[(t0 + i) * PDK + d];
        #pragma unroll
        for (int j = 0; j < 16; j++) {
            float sv = sS[d * PDV + j0 + j];
            #pragma unroll
            for (int i = 0; i < 4; i++) acc[i][j] += a[i] * sv;
        }
    }
    #pragma unroll
    for (int i = 0; i < 4; i++) {
        int t = t0 + i;
        int pos = dir ? (NN - 1 - (c * CH + t)) : (c * CH + t);
        float* dst = &g_od[dir][((size_t)(b * 4 + h) * NN + pos) * 256 + j0];
        #pragma unroll
        for (int j = 0; j < 16; j++) dst[j] += acc[i][j];
    }
}

// ---------------- combine: rmsnorm(o_f)+rmsnorm(o_b), silu(g) gate ----------------
__global__ void __launch_bounds__(256) combine_kernel(
    const float* __restrict__ gn, const float* __restrict__ ln)
{
    int idx = blockIdx.x;            // bh*NN + n
    int n = idx % NN;
    int bh = idx / NN;
    int h = bh & 3;
    int b = bh >> 2;
    int j = threadIdx.x;

    size_t rbase = ((size_t)bh * NN + n) * 256;
    float f  = g_od[0][rbase + j];
    float bo = g_od[1][rbase + j];

    float sf = f * f, sb = bo * bo;
    #pragma unroll
    for (int o = 16; o; o >>= 1) {
        sf += __shfl_down_sync(0xFFFFFFFFu, sf, o);
        sb += __shfl_down_sync(0xFFFFFFFFu, sb, o);
    }
    __shared__ float wf[8], wb[8], tot[2];
    int lane = j & 31, wid = j >> 5;
    if (lane == 0) { wf[wid] = sf; wb[wid] = sb; }
    __syncthreads();
    if (j == 0) {
        float a = 0.f, bq = 0.f;
        #pragma unroll
        for (int i = 0; i < 8; i++) { a += wf[i]; bq += wb[i]; }
        tot[0] = a; tot[1] = bq;
    }
    __syncthreads();
    float msf = tot[0] * (1.f / 256.f);
    float msb = tot[1] * (1.f / 256.f);
    float val = f * rsqrtf(msf + 1e-5f) * gn[j] + bo * rsqrtf(msb + 1e-5f) * ln[j];
    size_t gi = ((size_t)(b * NN + n)) * 1024 + h * 256 + j;
    float gv = g_g[gi];
    g_ob[gi] = gv / (1.f + expf(-gv)) * val;
}

// ---------------- launch ----------------
extern "C" void kernel_launch(void* const* d_in, const int* in_sizes, int n_in,
                              void* d_out, int out_size)
{
    const float* x      = (const float*)d_in[0];
    const float* conv_w = (const float*)d_in[1];
    const float* qkv_w  = (const float*)d_in[2];
    const float* gk_w1  = (const float*)d_in[3];
    const float* gk_w2  = (const float*)d_in[4];
    const float* gk_b2  = (const float*)d_in[5];
    const float* g_w    = (const float*)d_in[6];
    const float* g_b    = (const float*)d_in[7];
    const float* gnorm  = (const float*)d_in[8];
    const float* lnorm  = (const float*)d_in[9];
    const float* o_w    = (const float*)d_in[10];
    float* out = (float*)d_out;

    float *p_xs, *p_qkv, *p_g, *p_ob, *p_t16, *p_gk;
    cudaGetSymbolAddress((void**)&p_xs,  g_xs);
    cudaGetSymbolAddress((void**)&p_qkv, g_qkv);
    cudaGetSymbolAddress((void**)&p_g,   g_g);
    cudaGetSymbolAddress((void**)&p_ob,  g_ob);
    cudaGetSymbolAddress((void**)&p_t16, g_t16);
    cudaGetSymbolAddress((void**)&p_gk,  g_gk);

    cudaFuncSetAttribute(gla1_kernel, cudaFuncAttributeMaxDynamicSharedMemorySize,
                         SM1_FLOATS * (int)sizeof(float));
    cudaFuncSetAttribute(gla3_kernel, cudaFuncAttributeMaxDynamicSharedMemorySize,
                         SM3_FLOATS * (int)sizeof(float));

    // 1. conv + silu
    conv_silu_kernel<<<(MTOT * DM) / 256, 256>>>(x, conv_w);
    // 2. qkv GEMM
    gemm_nt_kernel<<<dim3(2048 / 128, MTOT / 128), 256>>>(p_xs, qkv_w, nullptr, p_qkv, 512, 2048, 0);
    // 3. low-rank gates: t16 = xs @ w1^T, then gk = logsigmoid(t16 @ w2^T + b2)/16 via GEMM
    lowrank1_kernel<<<MTOT / 64, 256>>>(gk_w1);
    gemm_nt_kernel<<<dim3(1024 / 128, MTOT / 128), 256>>>(p_t16, gk_w2, gk_b2, p_gk, 16, 1024, 1);
    // 4. output-gate GEMM
    gemm_nt_kernel<<<dim3(1024 / 128, MTOT / 128), 256>>>(p_xs, g_w, g_b, p_g, 512, 1024, 0);
    // 5. GLA
    gla1_kernel<<<NSEQ * NC, 256, SM1_FLOATS * sizeof(float)>>>();
    gla_scan_kernel<<<(NSEQ * 128 * 256) / 256, 256>>>();
    gla3_kernel<<<NSEQ * NC, 256, SM3_FLOATS * sizeof(float)>>>();
    // 6. norms + gating
    combine_kernel<<<32 * NN, 256>>>(gnorm, lnorm);
    // 7. output projection
    gemm_nt_kernel<<<dim3(512 / 128, MTOT / 128), 256>>>(p_ob, o_w, nullptr, out, 1024, 512, 0);

    (void)in_sizes; (void)n_in; (void)out_size;
}

// round 11
// speedup vs baseline: 1.5819x; 1.5819x over previous
#include <cuda_runtime.h>
#include <cuda_bf16.h>
#include <math.h>
#include <stdint.h>

// ---------------- problem constants ----------------
#define BB   8
#define NN   3136        // 56*56
#define DM   512
#define NH   4
#define DK   128         // head_qk
#define DV   256         // head_v
#define CH   64          // chunk
#define NC   49          // chunks per sequence
#define MTOT (BB*NN)     // 25088
#define NSEQ 64          // 2 dir * 8 b * 4 h

// padded smem strides (GLA kernels)
#define PDK 132
#define PDV 260
#define PCH 68

// ---------------- scratch (device globals; no allocation) ----------------
__device__ float g_xs  [MTOT * DM];          // conv+silu output
__device__ float g_qkv [MTOT * 2048];        // q(512) k(512) v(1024)
__device__ float g_t16 [MTOT * 16];          // low-rank intermediate
__device__ float g_gk  [MTOT * 1024];        // gates (f 512 | b 512), log-sig/16
__device__ float g_g   [MTOT * 1024];        // output gate pre-silu
__device__ float g_qe  [(size_t)NSEQ * NN * DK];    // decayed scaled q per seq
__device__ float g_od  [2][(size_t)32 * NN * DV];   // o_fwd / o_bwd (orig positions)
__device__ float g_S   [(size_t)NSEQ * NC * DK * DV]; // local states -> prefix states
__device__ float g_dec [NSEQ * NC * DK];     // per-chunk decay exp(btot)
__device__ float g_ob  [MTOT * 1024];        // gated combined output

// ---------------- depthwise conv 3x3 + SiLU ----------------
__global__ void __launch_bounds__(256) conv_silu_kernel(
    const float* __restrict__ x, const float* __restrict__ w)
{
    int idx = blockIdx.x * 256 + threadIdx.x;       // over MTOT*512
    int c = idx & 511;
    int m = idx >> 9;
    int b = m / NN;
    int n = m - b * NN;
    int h = n / 56, ww = n - h * 56;
    float acc = 0.f;
    #pragma unroll
    for (int dh = -1; dh <= 1; dh++) {
        int hh = h + dh;
        if ((unsigned)hh >= 56u) continue;
        #pragma unroll
        for (int dw = -1; dw <= 1; dw++) {
            int w2 = ww + dw;
            if ((unsigned)w2 >= 56u) continue;
            acc += x[(((size_t)b * NN + hh * 56 + w2) << 9) + c] * w[c * 9 + (dh + 1) * 3 + (dw + 1)];
        }
    }
    g_xs[idx] = acc / (1.f + expf(-acc));
}

// ---------------- tf32 tensor-core GEMM ----------------
// C[M,Nc] = A[M,K] * B[Nc,K]^T (+bias, act==1: logsigmoid/16)
// 128x128x16 tiles, 256 threads (8 warps, 64x32 warp tiles), mma.m16n8k8.tf32.
// smem layout: per 8-k group, k' = (k&3)*2 + (k>>2)  => fragment pairs (c, c+4)
// are adjacent => single LDS.64 per fragment half. PKS=24 => conflict-free.
#define PKS 24
__device__ __forceinline__ float to_tf32(float x) {
    uint32_t u;
    asm("cvt.rna.tf32.f32 %0, %1;" : "=r"(u) : "f"(x));
    return __uint_as_float(u);
}
__device__ __forceinline__ void mma_tf32(float* c,
    uint32_t a0, uint32_t a1, uint32_t a2, uint32_t a3, uint32_t b0, uint32_t b1)
{
    asm volatile(
        "mma.sync.aligned.m16n8k8.row.col.f32.tf32.tf32.f32 "
        "{%0,%1,%2,%3},{%4,%5,%6,%7},{%8,%9},{%0,%1,%2,%3};"
        : "+f"(c[0]), "+f"(c[1]), "+f"(c[2]), "+f"(c[3])
        : "r"(a0), "r"(a1), "r"(a2), "r"(a3), "r"(b0), "r"(b1));
}

__global__ void __launch_bounds__(256) gemm_tf32_kernel(
    const float* __restrict__ A, const float* __restrict__ Bm,
    const float* __restrict__ bias, float* __restrict__ C, int K, int Nc, int act)
{
    __shared__ float As[128 * PKS];
    __shared__ float Bs[128 * PKS];
    const int tid = threadIdx.x;
    const int m0 = blockIdx.y * 128;
    const int n0 = blockIdx.x * 128;
    const int lane = tid & 31;
    const int w = tid >> 5;
    const int wm = (w >> 2) * 64;       // 2 warps along M
    const int wn = (w & 3) * 32;        // 4 warps along N

    // staging map: 512 float4 slots per matrix per BK=16; 2 per thread
    int arow[2], akq[2];
    #pragma unroll
    for (int i = 0; i < 2; i++) {
        int idx = tid * 2 + i;
        arow[i] = idx >> 2;
        akq[i] = (idx & 3) << 2;
    }
    const float* Ap0 = A + (size_t)(m0 + arow[0]) * K + akq[0];
    const float* Ap1 = A + (size_t)(m0 + arow[1]) * K + akq[1];
    const float* Bp0 = Bm + (size_t)(n0 + arow[0]) * K + akq[0];
    const float* Bp1 = Bm + (size_t)(n0 + arow[1]) * K + akq[1];

    float acc[4][4][4];                 // [mt][nt][frag]
    #pragma unroll
    for (int i = 0; i < 4; i++)
        #pragma unroll
        for (int j = 0; j < 4; j++)
            #pragma unroll
            for (int q = 0; q < 4; q++) acc[i][j][q] = 0.f;

    float4 av[2], bv[2];
    av[0] = *(const float4*)Ap0; av[1] = *(const float4*)Ap1;
    bv[0] = *(const float4*)Bp0; bv[1] = *(const float4*)Bp1;

    for (int k0 = 0; k0 < K; k0 += 16) {
        // stage with tf32 rounding + k-permutation
        #pragma unroll
        for (int i = 0; i < 2; i++) {
            float e[4] = {av[i].x, av[i].y, av[i].z, av[i].w};
            float f[4] = {bv[i].x, bv[i].y, bv[i].z, bv[i].w};
            #pragma unroll
            for (int q = 0; q < 4; q++) {
                int k = akq[i] + q;
                int kin = k & 7;
                int kp = (k >> 3) * 8 + (kin & 3) * 2 + (kin >> 2);
                As[arow[i] * PKS + kp] = to_tf32(e[q]);
                Bs[arow[i] * PKS + kp] = to_tf32(f[q]);
            }
        }
        __syncthreads();
        if (k0 + 16 < K) {               // prefetch next tile
            av[0] = *(const float4*)(Ap0 + k0 + 16);
            av[1] = *(const float4*)(Ap1 + k0 + 16);
            bv[0] = *(const float4*)(Bp0 + k0 + 16);
            bv[1] = *(const float4*)(Bp1 + k0 + 16);
        }
        #pragma unroll
        for (int ks = 0; ks < 2; ks++) {
            const int koff = ks * 8 + 2 * (lane & 3);
            uint32_t af[4][4];
            #pragma unroll
            for (int mt = 0; mt < 4; mt++) {
                int r = wm + mt * 16 + (lane >> 2);
                float2 lo = *(const float2*)&As[r * PKS + koff];
                float2 hi = *(const float2*)&As[(r + 8) * PKS + koff];
                af[mt][0] = __float_as_uint(lo.x);
                af[mt][2] = __float_as_uint(lo.y);
                af[mt][1] = __float_as_uint(hi.x);
                af[mt][3] = __float_as_uint(hi.y);
            }
            uint32_t bf[4][2];
            #pragma unroll
            for (int nt = 0; nt < 4; nt++) {
                int nr = wn + nt * 8 + (lane >> 2);
                float2 bb = *(const float2*)&Bs[nr * PKS + koff];
                bf[nt][0] = __float_as_uint(bb.x);
                bf[nt][1] = __float_as_uint(bb.y);
            }
            #pragma unroll
            for (int mt = 0; mt < 4; mt++)
                #pragma unroll
                for (int nt = 0; nt < 4; nt++)
                    mma_tf32(acc[mt][nt], af[mt][0], af[mt][1], af[mt][2], af[mt][3],
                             bf[nt][0], bf[nt][1]);
        }
        __syncthreads();
    }

    // epilogue
    #pragma unroll
    for (int mt = 0; mt < 4; mt++) {
        int r0 = m0 + wm + mt * 16 + (lane >> 2);
        #pragma unroll
        for (int nt = 0; nt < 4; nt++) {
            int cb = n0 + wn + nt * 8 + 2 * (lane & 3);
            float v0 = acc[mt][nt][0], v1 = acc[mt][nt][1];
            float v2 = acc[mt][nt][2], v3 = acc[mt][nt][3];
            if (bias) {
                float b0 = bias[cb], b1 = bias[cb + 1];
                v0 += b0; v1 += b1; v2 += b0; v3 += b1;
            }
            if (act == 1) {
                v0 = (fminf(v0, 0.f) - log1pf(expf(-fabsf(v0)))) * (1.f / 16.f);
                v1 = (fminf(v1, 0.f) - log1pf(expf(-fabsf(v1)))) * (1.f / 16.f);
                v2 = (fminf(v2, 0.f) - log1pf(expf(-fabsf(v2)))) * (1.f / 16.f);
                v3 = (fminf(v3, 0.f) - log1pf(expf(-fabsf(v3)))) * (1.f / 16.f);
            }
            float2 p0 = {v0, v1}, p1 = {v2, v3};
            *(float2*)&C[(size_t)r0 * Nc + cb] = p0;
            *(float2*)&C[(size_t)(r0 + 8) * Nc + cb] = p1;
        }
    }
}

// ---------------- low-rank gate, stage 1: t16 = xs @ gk_w1^T ----------------
__global__ void __launch_bounds__(256) lowrank1_kernel(const float* __restrict__ w1)
{
    __shared__ float w1t[128][16];   // transposed chunk of w1: [c][r]
    __shared__ float xs_s[64][129];  // xs chunk, padded stride
    const int tid = threadIdx.x;
    const int m0 = blockIdx.x * 64;
    const int tx = tid & 15;         // r index
    const int ty = tid >> 4;         // row group (4 rows each)

    float acc[4] = {};

    for (int c0 = 0; c0 < 512; c0 += 128) {
        for (int e = tid; e < 128 * 16; e += 256) {
            int c = e >> 4, r = e & 15;
            w1t[c][r] = w1[r * 512 + c0 + c];
        }
        for (int e = tid; e < 64 * 32; e += 256) {
            int row = e >> 5, cq = (e & 31) << 2;
            float4 v = *(const float4*)&g_xs[(size_t)(m0 + row) * 512 + c0 + cq];
            xs_s[row][cq + 0] = v.x; xs_s[row][cq + 1] = v.y;
            xs_s[row][cq + 2] = v.z; xs_s[row][cq + 3] = v.w;
        }
        __syncthreads();
        #pragma unroll 4
        for (int c = 0; c < 128; c++) {
            float w = w1t[c][tx];
            #pragma unroll
            for (int i = 0; i < 4; i++)
                acc[i] += xs_s[ty * 4 + i][c] * w;
        }
        __syncthreads();
    }
    #pragma unroll
    for (int i = 0; i < 4; i++)
        g_t16[(m0 + ty * 4 + i) * 16 + tx] = acc[i];
}

// ---------------- GLA phase 1: per-chunk intra attention + local state ----------------
#define SM1_FLOATS (3 * 64 * PDK + 64 * PDV + 64 * PCH + 128)
__global__ void __launch_bounds__(256) gla1_kernel()
{
    extern __shared__ float sm[];
    float* sB = sm;                   // [64][PDK] cumsum gates
    float* sQ = sB + 64 * PDK;        // [64][PDK] qe
    float* sK = sQ + 64 * PDK;        // [64][PDK] k*exp(-b)
    float* sV = sK + 64 * PDK;        // [64][PDV] v
    float* sA = sV + 64 * PDV;        // [64][PCH] masked scores
    float* sE = sA + 64 * PCH;        // [128] exp(btot)

    const int blk = blockIdx.x;
    const int c = blk % NC;
    const int seq = blk / NC;
    const int h = seq & 3;
    const int b = (seq >> 2) & 7;
    const int dir = seq >> 5;
    const int tid = threadIdx.x;

    for (int e = tid; e < 64 * 128; e += 256) {
        int t = e >> 7, d = e & 127;
        int pos = dir ? (NN - 1 - (c * CH + t)) : (c * CH + t);
        sB[t * PDK + d] = g_gk[((size_t)(b * NN + pos)) * 1024 + dir * 512 + h * 128 + d];
    }
    __syncthreads();
    if (tid < 128) {
        float run = sB[tid];
        for (int t = 1; t < 64; t++) { run += sB[t * PDK + tid]; sB[t * PDK + tid] = run; }
        float eb = expf(run);
        sE[tid] = eb;
        g_dec[(seq * NC + c) * 128 + tid] = eb;
    }
    __syncthreads();
    const float scale = 0.08838834764831845f;   // 128^-0.5
    for (int e = tid; e < 64 * 128; e += 256) {
        int t = e >> 7, d = e & 127;
        int pos = dir ? (NN - 1 - (c * CH + t)) : (c * CH + t);
        float bb = sB[t * PDK + d];
        size_t rowq = ((size_t)(b * NN + pos)) * 2048 + h * 128 + d;
        float qe = g_qkv[rowq] * expf(bb) * scale;
        float ke = g_qkv[rowq + 512] * expf(-bb);
        sQ[t * PDK + d] = qe;
        sK[t * PDK + d] = ke;
        g_qe[((size_t)seq * NN + c * CH + t) * 128 + d] = qe;
    }
    for (int e = tid; e < 64 * 256; e += 256) {
        int t = e >> 8, j = e & 255;
        int pos = dir ? (NN - 1 - (c * CH + t)) : (c * CH + t);
        sV[t * PDV + j] = g_qkv[((size_t)(b * NN + pos)) * 2048 + 1024 + h * 256 + j];
    }
    __syncthreads();

    const int tx = tid & 15, ty = tid >> 4;
    {
        float acc[4][4] = {};
        for (int d = 0; d < 128; d++) {
            float a[4], bb[4];
            #pragma unroll
            for (int i = 0; i < 4; i++) a[i] = sQ[(ty * 4 + i) * PDK + d];
            #pragma unroll
            for (int j = 0; j < 4; j++) bb[j] = sK[(tx * 4 + j) * PDK + d];
            #pragma unroll
            for (int i = 0; i < 4; i++)
                #pragma unroll
                for (int j = 0; j < 4; j++) acc[i][j] += a[i] * bb[j];
        }
        #pragma unroll
        for (int i = 0; i < 4; i++)
            #pragma unroll
            for (int j = 0; j < 4; j++) {
                int t = ty * 4 + i, s = tx * 4 + j;
                sA[t * PCH + s] = (t >= s) ? acc[i][j] : 0.f;
            }
    }
    __syncthreads();
    {
        float acc[4][16] = {};
        int t0 = ty * 4, j0 = tx * 16;
        for (int s = 0; s < 64; s++) {
            float a[4];
            #pragma unroll
            for (int i = 0; i < 4; i++) a[i] = sA[(t0 + i) * PCH + s];
            #pragma unroll
            for (int j = 0; j < 16; j++) {
                float vv = sV[s * PDV + j0 + j];
                #pragma unroll
                for (int i = 0; i < 4; i++) acc[i][j] += a[i] * vv;
            }
        }
        #pragma unroll
        for (int i = 0; i < 4; i++) {
            int t = t0 + i;
            int pos = dir ? (NN - 1 - (c * CH + t)) : (c * CH + t);
            float* dst = &g_od[dir][((size_t)(b * 4 + h) * NN + pos) * 256 + j0];
            #pragma unroll
            for (int j = 0; j < 16; j++) dst[j] = acc[i][j];
        }
    }
    {
        int d0 = ty * 8;
        for (int jh = 0; jh < 2; jh++) {
            int j0 = jh * 128 + tx * 8;
            float acc[8][8] = {};
            for (int s = 0; s < 64; s++) {
                float kv[8], vv[8];
                #pragma unroll
                for (int i = 0; i < 8; i++) kv[i] = sK[s * PDK + d0 + i];
                #pragma unroll
                for (int j = 0; j < 8; j++) vv[j] = sV[s * PDV + j0 + j];
                #pragma unroll
                for (int i = 0; i < 8; i++)
                    #pragma unroll
                    for (int j = 0; j < 8; j++) acc[i][j] += kv[i] * vv[j];
            }
            size_t base = ((size_t)(seq * NC + c)) * 32768;
            #pragma unroll
            for (int i = 0; i < 8; i++) {
                float eb = sE[d0 + i];
                #pragma unroll
                for (int j = 0; j < 8; j++)
                    g_S[base + (d0 + i) * 256 + j0 + j] = eb * acc[i][j];
            }
        }
    }
}

// ---------------- GLA phase 2: sequential scan over chunks (in place) ----------------
__global__ void __launch_bounds__(256) gla_scan_kernel()
{
    int g = blockIdx.x * 256 + threadIdx.x;     // < NSEQ*128*256
    int j = g & 255;
    int d = (g >> 8) & 127;
    int seq = g >> 15;
    float S = 0.f;
    size_t base = (size_t)seq * NC * 32768 + d * 256 + j;
    int dbase = seq * NC * 128 + d;
    for (int c = 0; c < NC; c++) {
        float loc = g_S[base + (size_t)c * 32768];
        float dec = g_dec[dbase + c * 128];
        g_S[base + (size_t)c * 32768] = S;       // prefix (state BEFORE chunk c)
        S = S * dec + loc;
    }
}

// ---------------- GLA phase 3: o += qe @ S_prefix ----------------
#define SM3_FLOATS (64 * PDK + 128 * PDV)
__global__ void __launch_bounds__(256) gla3_kernel()
{
    const int blk = blockIdx.x;
    const int c = blk % NC;
    if (c == 0) return;                          // prefix is zero
    const int seq = blk / NC;
    const int h = seq & 3;
    const int b = (seq >> 2) & 7;
    const int dir = seq >> 5;
    const int tid = threadIdx.x;

    extern __shared__ float sm[];
    float* sQ = sm;                  // [64][PDK]
    float* sS = sQ + 64 * PDK;       // [128][PDV]

    for (int e = tid; e < 64 * 128; e += 256) {
        int t = e >> 7, d = e & 127;
        sQ[t * PDK + d] = g_qe[((size_t)seq * NN + c * CH + t) * 128 + d];
    }
    size_t sbase = ((size_t)(seq * NC + c)) * 32768;
    for (int e = tid; e < 128 * 256; e += 256) {
        int d = e >> 8, j = e & 255;
        sS[d * PDV + j] = g_S[sbase + e];
    }
    __syncthreads();

    const int tx = tid & 15, ty = tid >> 4;
    int t0 = ty * 4, j0 = tx * 16;
    float acc[4][16] = {};
    for (int d = 0; d < 128; d++) {
        float a[4];
        #pragma unroll
        for (int i = 0; i < 4; i++) a[i] = sQ[(t0 + i) * PDK + d];
        #pragma unroll
        for (int j = 0; j < 16; j++) {
            float sv = sS[d * PDV + j0 + j];
            #pragma unroll
            for (int i = 0; i < 4; i++) acc[i][j] += a[i] * sv;
        }
    }
    #pragma unroll
    for (int i = 0; i < 4; i++) {
        int t = t0 + i;
        int pos = dir ? (NN - 1 - (c * CH + t)) : (c * CH + t);
        float* dst = &g_od[dir][((size_t)(b * 4 + h) * NN + pos) * 256 + j0];
        #pragma unroll
        for (int j = 0; j < 16; j++) dst[j] += acc[i][j];
    }
}

// ---------------- combine: rmsnorm(o_f)+rmsnorm(o_b), silu(g) gate ----------------
__global__ void __launch_bounds__(256) combine_kernel(
    const float* __restrict__ gn, const float* __restrict__ ln)
{
    int idx = blockIdx.x;            // bh*NN + n
    int n = idx % NN;
    int bh = idx / NN;
    int h = bh & 3;
    int b = bh >> 2;
    int j = threadIdx.x;

    size_t rbase = ((size_t)bh * NN + n) * 256;
    float f  = g_od[0][rbase + j];
    float bo = g_od[1][rbase + j];

    float sf = f * f, sb = bo * bo;
    #pragma unroll
    for (int o = 16; o; o >>= 1) {
        sf += __shfl_down_sync(0xFFFFFFFFu, sf, o);
        sb += __shfl_down_sync(0xFFFFFFFFu, sb, o);
    }
    __shared__ float wf[8], wb[8], tot[2];
    int lane = j & 31, wid = j >> 5;
    if (lane == 0) { wf[wid] = sf; wb[wid] = sb; }
    __syncthreads();
    if (j == 0) {
        float a = 0.f, bq = 0.f;
        #pragma unroll
        for (int i = 0; i < 8; i++) { a += wf[i]; bq += wb[i]; }
        tot[0] = a; tot[1] = bq;
    }
    __syncthreads();
    float msf = tot[0] * (1.f / 256.f);
    float msb = tot[1] * (1.f / 256.f);
    float val = f * rsqrtf(msf + 1e-5f) * gn[j] + bo * rsqrtf(msb + 1e-5f) * ln[j];
    size_t gi = ((size_t)(b * NN + n)) * 1024 + h * 256 + j;
    float gv = g_g[gi];
    g_ob[gi] = gv / (1.f + expf(-gv)) * val;
}

// ---------------- launch ----------------
extern "C" void kernel_launch(void* const* d_in, const int* in_sizes, int n_in,
                              void* d_out, int out_size)
{
    const float* x      = (const float*)d_in[0];
    const float* conv_w = (const float*)d_in[1];
    const float* qkv_w  = (const float*)d_in[2];
    const float* gk_w1  = (const float*)d_in[3];
    const float* gk_w2  = (const float*)d_in[4];
    const float* gk_b2  = (const float*)d_in[5];
    const float* g_w    = (const float*)d_in[6];
    const float* g_b    = (const float*)d_in[7];
    const float* gnorm  = (const float*)d_in[8];
    const float* lnorm  = (const float*)d_in[9];
    const float* o_w    = (const float*)d_in[10];
    float* out = (float*)d_out;

    float *p_xs, *p_qkv, *p_g, *p_ob, *p_t16, *p_gk;
    cudaGetSymbolAddress((void**)&p_xs,  g_xs);
    cudaGetSymbolAddress((void**)&p_qkv, g_qkv);
    cudaGetSymbolAddress((void**)&p_g,   g_g);
    cudaGetSymbolAddress((void**)&p_ob,  g_ob);
    cudaGetSymbolAddress((void**)&p_t16, g_t16);
    cudaGetSymbolAddress((void**)&p_gk,  g_gk);

    cudaFuncSetAttribute(gla1_kernel, cudaFuncAttributeMaxDynamicSharedMemorySize,
                         SM1_FLOATS * (int)sizeof(float));
    cudaFuncSetAttribute(gla3_kernel, cudaFuncAttributeMaxDynamicSharedMemorySize,
                         SM3_FLOATS * (int)sizeof(float));

    // 1. conv + silu
    conv_silu_kernel<<<(MTOT * DM) / 256, 256>>>(x, conv_w);
    // 2. qkv GEMM (tf32 tensor core)
    gemm_tf32_kernel<<<dim3(2048 / 128, MTOT / 128), 256>>>(p_xs, qkv_w, nullptr, p_qkv, 512, 2048, 0);
    // 3. low-rank gates: t16 = xs @ w1^T, then gk = logsigmoid(t16 @ w2^T + b2)/16
    lowrank1_kernel<<<MTOT / 64, 256>>>(gk_w1);
    gemm_tf32_kernel<<<dim3(1024 / 128, MTOT / 128), 256>>>(p_t16, gk_w2, gk_b2, p_gk, 16, 1024, 1);
    // 4. output-gate GEMM
    gemm_tf32_kernel<<<dim3(1024 / 128, MTOT / 128), 256>>>(p_xs, g_w, g_b, p_g, 512, 1024, 0);
    // 5. GLA
    gla1_kernel<<<NSEQ * NC, 256, SM1_FLOATS * sizeof(float)>>>();
    gla_scan_kernel<<<(NSEQ * 128 * 256) / 256, 256>>>();
    gla3_kernel<<<NSEQ * NC, 256, SM3_FLOATS * sizeof(float)>>>();
    // 6. norms + gating
    combine_kernel<<<32 * NN, 256>>>(gnorm, lnorm);
    // 7. output projection
    gemm_tf32_kernel<<<dim3(512 / 128, MTOT / 128), 256>>>(p_ob, o_w, nullptr, out, 1024, 512, 0);

    (void)in_sizes; (void)n_in; (void)out_size;
}